// round 7
// baseline (speedup 1.0000x reference)
#include <cuda_runtime.h>
#include <cstdint>
#include <math.h>

#define NH   32
#define HD   128
#define BB   4
#define QL   64
#define CTX  4096
#define HID  4096
#define TOTAL_KV (CTX + QL)
#define NTILE (TOTAL_KV / 64)    // 65

__device__ float g_qproj[BB * QL * HID];
__device__ float g_q[BB * NH * QL * HD];
__device__ float g_attn[BB * QL * HID];

__device__ __forceinline__ uint32_t smem_u32(const void* p) {
    uint32_t a;
    asm("{ .reg .u64 t; cvta.to.shared.u64 t, %1; cvt.u32.u64 %0, t; }" : "=r"(a) : "l"(p));
    return a;
}
__device__ __forceinline__ void ldsm4(uint32_t* r, uint32_t a) {
    asm volatile("ldmatrix.sync.aligned.m8n8.x4.shared.b16 {%0,%1,%2,%3}, [%4];"
        : "=r"(r[0]), "=r"(r[1]), "=r"(r[2]), "=r"(r[3]) : "r"(a));
}
__device__ __forceinline__ void ldsm4t(uint32_t* r, uint32_t a) {
    asm volatile("ldmatrix.sync.aligned.m8n8.x4.trans.shared.b16 {%0,%1,%2,%3}, [%4];"
        : "=r"(r[0]), "=r"(r[1]), "=r"(r[2]), "=r"(r[3]) : "r"(a));
}
__device__ __forceinline__ void mma16816(float* c, const uint32_t* a, const uint32_t* b) {
    asm volatile(
        "mma.sync.aligned.m16n8k16.row.col.f32.bf16.bf16.f32 "
        "{%0,%1,%2,%3}, {%4,%5,%6,%7}, {%8,%9}, {%0,%1,%2,%3};"
        : "+f"(c[0]), "+f"(c[1]), "+f"(c[2]), "+f"(c[3])
        : "r"(a[0]), "r"(a[1]), "r"(a[2]), "r"(a[3]), "r"(b[0]), "r"(b[1]));
}
__device__ __forceinline__ void split_pack(float e0, float e1, uint32_t& hi, uint32_t& lo) {
    uint32_t h;
    asm("cvt.rn.bf16x2.f32 %0, %1, %2;" : "=r"(h) : "f"(e1), "f"(e0));
    float f0 = __uint_as_float(h << 16);
    float f1 = __uint_as_float(h & 0xffff0000u);
    uint32_t l;
    asm("cvt.rn.bf16x2.f32 %0, %1, %2;" : "=r"(l) : "f"(e1 - f1), "f"(e0 - f0));
    hi = h; lo = l;
}
#define CPA16(d, s) asm volatile("cp.async.cg.shared.global [%0], [%1], 16;" :: "r"(d), "l"(s))
#define CPC()  asm volatile("cp.async.commit_group;" ::: "memory")
#define CPW1() asm volatile("cp.async.wait_group 1;" ::: "memory")
#define NBAR(id) asm volatile("bar.sync %0, %1;" :: "r"(id), "r"(128) : "memory")

// ===========================================================================
// bf16-split GEMM v2 (ks-split warps): C[256,N] = A[256,K] @ W[K,N]
// block 128m x 64n, BK=32, 256 thr, 8 warps = (wm2 x wn2 x wks2),
// warp tile 64m x 32n over one 16-k half-chunk; partial acc summed at end.
// LDG/STS paths identical to validated R4 kernel.
// ===========================================================================
#define AST 40
#define WST 72
#define ABYTES (128 * AST * 2)
#define WBYTES (32 * WST * 2)
#define STAGE  (2 * ABYTES + 2 * WBYTES)
#define GSMEM  (2 * STAGE)

#define GEMM_LDG(c) do { \
  _Pragma("unroll") for (int q = 0; q < 4; q++) { int i = t + q * 256; \
    ra[q] = *(const float4*)(A + (size_t)(m0 + (i >> 3)) * K + (c) * 32 + (i & 7) * 4); } \
  _Pragma("unroll") for (int q = 0; q < 2; q++) { int i = t + q * 256; \
    rw[q] = *(const float4*)(W + (size_t)((c) * 32 + (i >> 4)) * ldb + n0 + (i & 15) * 4); } \
} while (0)

#define GEMM_STS(bufp) do { \
  _Pragma("unroll") for (int q = 0; q < 4; q++) { int i = t + q * 256; \
    int row = i >> 3, kc = (i & 7) * 4; uint32_t h0, l0, h1, l1; \
    split_pack(ra[q].x, ra[q].y, h0, l0); split_pack(ra[q].z, ra[q].w, h1, l1); \
    uint32_t off = (uint32_t)(row * AST + kc) * 2; \
    *(uint2*)((bufp) + off) = make_uint2(h0, h1); \
    *(uint2*)((bufp) + ABYTES + off) = make_uint2(l0, l1); } \
  _Pragma("unroll") for (int q = 0; q < 2; q++) { int i = t + q * 256; \
    int kr = i >> 4, nc = (i & 15) * 4; uint32_t h0, l0, h1, l1; \
    split_pack(rw[q].x, rw[q].y, h0, l0); split_pack(rw[q].z, rw[q].w, h1, l1); \
    uint32_t off = (uint32_t)(kr * WST + nc) * 2; \
    *(uint2*)((bufp) + 2 * ABYTES + off) = make_uint2(h0, h1); \
    *(uint2*)((bufp) + 2 * ABYTES + WBYTES + off) = make_uint2(l0, l1); } \
} while (0)

__global__ __launch_bounds__(256) void gemm_bf16s(
    const float* __restrict__ A, const float* __restrict__ W,
    float* __restrict__ C, int K, int N, int ldb)
{
    extern __shared__ __align__(16) char smc[];
    const uint32_t smb = smem_u32(smc);
    const int t = threadIdx.x, w = t >> 5, L = t & 31, g = L >> 3, r8 = L & 7;
    const int wm = (w >> 2) & 1, wn = (w >> 1) & 1, wks = w & 1;
    const int m0 = blockIdx.y * 128, n0 = blockIdx.x * 64;
    const int NCH = K / 32;

    float4 ra[4]; float4 rw[2];
    float acc[4][4][4] = {};

    GEMM_LDG(0);
    GEMM_STS(smc);
    __syncthreads();
    if (NCH > 1) GEMM_LDG(1);

    for (int c = 0; c < NCH; c++) {
        const uint32_t sb = smb + (uint32_t)(c & 1) * STAGE;
        uint32_t ah[4][4], al[4][4], bh[4][2], bl[4][2];
#pragma unroll
        for (int mf = 0; mf < 4; mf++) {
            uint32_t ad = sb + (uint32_t)((wm * 64 + mf * 16 + (g & 1) * 8 + r8) * AST
                                          + wks * 16 + (g >> 1) * 8) * 2;
            ldsm4(ah[mf], ad);
            ldsm4(al[mf], ad + ABYTES);
        }
#pragma unroll
        for (int nt = 0; nt < 2; nt++) {
            int kk = wks * 16 + (L & 15);
            int nn = wn * 32 + nt * 16 + ((L >> 4) << 3);
            uint32_t bd = sb + 2 * ABYTES + (uint32_t)(kk * WST + nn) * 2;
            uint32_t r4[4];
            ldsm4t(r4, bd);
            bh[nt * 2][0] = r4[0]; bh[nt * 2][1] = r4[1];
            bh[nt * 2 + 1][0] = r4[2]; bh[nt * 2 + 1][1] = r4[3];
            ldsm4t(r4, bd + WBYTES);
            bl[nt * 2][0] = r4[0]; bl[nt * 2][1] = r4[1];
            bl[nt * 2 + 1][0] = r4[2]; bl[nt * 2 + 1][1] = r4[3];
        }
#pragma unroll
        for (int mf = 0; mf < 4; mf++)
#pragma unroll
            for (int nf = 0; nf < 4; nf++) {
                mma16816(acc[mf][nf], ah[mf], bh[nf]);
                mma16816(acc[mf][nf], ah[mf], bl[nf]);
                mma16816(acc[mf][nf], al[mf], bh[nf]);
            }
        if (c + 1 < NCH) {
            GEMM_STS(smc + ((c + 1) & 1) * STAGE);
            if (c + 2 < NCH) GEMM_LDG(c + 2);
        }
        __syncthreads();
    }

    // ---- ks-pair reduction via smem, then C store ----
    float* red = (float*)smc;
    if (wks == 0) {
#pragma unroll
        for (int mf = 0; mf < 4; mf++)
#pragma unroll
            for (int nf = 0; nf < 4; nf++) {
                int row = wm * 64 + mf * 16 + (L >> 2);
                int col = wn * 32 + nf * 8 + (L & 3) * 2;
                *(float2*)&red[row * 66 + col] = make_float2(acc[mf][nf][0], acc[mf][nf][1]);
                *(float2*)&red[(row + 8) * 66 + col] = make_float2(acc[mf][nf][2], acc[mf][nf][3]);
            }
    }
    __syncthreads();
    if (wks == 1) {
#pragma unroll
        for (int mf = 0; mf < 4; mf++)
#pragma unroll
            for (int nf = 0; nf < 4; nf++) {
                int row = wm * 64 + mf * 16 + (L >> 2);
                int col = wn * 32 + nf * 8 + (L & 3) * 2;
                float2 p0 = *(float2*)&red[row * 66 + col];
                float2 p1 = *(float2*)&red[(row + 8) * 66 + col];
                *(float2*)&C[(size_t)(m0 + row) * N + n0 + col] =
                    make_float2(acc[mf][nf][0] + p0.x, acc[mf][nf][1] + p0.y);
                *(float2*)&C[(size_t)(m0 + row + 8) * N + n0 + col] =
                    make_float2(acc[mf][nf][2] + p1.x, acc[mf][nf][3] + p1.y);
            }
    }
}

// ---------------------------------------------------------------------------
// Fused double-RMSNorm + RoPE on Q (unchanged).
// ---------------------------------------------------------------------------
__global__ __launch_bounds__(128) void qnorm_rope_kernel(
    const float* __restrict__ qproj, const float* __restrict__ w,
    const float* __restrict__ cosp, const float* __restrict__ sinp,
    float* __restrict__ qout)
{
    const int blk = blockIdx.x;
    const int h = blk & 31;
    const int m = blk >> 5;
    const int b = m >> 6, q = m & 63;
    const int d = threadIdx.x;

    __shared__ float red[4];
    __shared__ float zbuf[128];

    float x = qproj[(size_t)m * HID + h * HD + d];
    float v = x * x;
#pragma unroll
    for (int o = 16; o > 0; o >>= 1) v += __shfl_down_sync(0xffffffffu, v, o);
    if ((d & 31) == 0) red[d >> 5] = v;
    __syncthreads();
    float mean1 = (red[0] + red[1] + red[2] + red[3]) * (1.0f / 128.0f);
    float y = x * rsqrtf(mean1 + 1e-6f) * w[d];
    __syncthreads();
    v = y * y;
#pragma unroll
    for (int o = 16; o > 0; o >>= 1) v += __shfl_down_sync(0xffffffffu, v, o);
    if ((d & 31) == 0) red[d >> 5] = v;
    __syncthreads();
    float mean2 = (red[0] + red[1] + red[2] + red[3]) * (1.0f / 128.0f);
    float z = y * rsqrtf(mean2 + 1e-6f) * w[d];
    zbuf[d] = z;
    __syncthreads();
    const int pos = CTX + q;
    float rot = (d < 64) ? -zbuf[d + 64] : zbuf[d - 64];
    qout[(((size_t)(b * NH + h) * QL) + q) * HD + d] =
        z * cosp[(size_t)pos * HD + d] + rot * sinp[(size_t)pos * HD + d];
}

// ===========================================================================
// Flash attention v4: named bar1 (per-wq group), rope before PV, K [pos][d].
// ===========================================================================
#define RAW0 0
#define RAW1 32768
#define KHO  65536          // KH(s) = KHO + s*34816, KL = KH + 17408
#define VHO  135168         // VH(s) = VHO + s*34816, VL = VH + 17408
#define PHO  204800         // [64][72] bf16 hi
#define PLO  214016         // lo
#define WMX  223232         // float [4][64]
#define WSM  224256         // float [4][64]
#define ATT_SMEM 225280

__global__ __launch_bounds__(512, 1) void attn_kernel(
    const float* __restrict__ qin, const float* __restrict__ target,
    const float* __restrict__ hidden, const float* __restrict__ cosp,
    const float* __restrict__ sinp, float* __restrict__ out)
{
    extern __shared__ __align__(16) char smc[];
    const uint32_t smb = smem_u32(smc);
    float* wmx = (float*)(smc + WMX);
    float* wsm = (float*)(smc + WSM);

    const int h = blockIdx.x, b = blockIdx.y;
    const int t = threadIdx.x, w = t >> 5, L = t & 31, g = L >> 3, r8 = L & 7;
    const int wq = w >> 2, wk = w & 3;
    const float scale = 0.08838834764831845f;

    // ---- stage Q (hi/lo) in RAW area, hoist fragments, then release ----
    const float* qb = qin + ((size_t)(b * NH + h) * QL) * HD;
#pragma unroll
    for (int i = 0; i < 8; i++) {
        int idx = t + i * 512, row = idx >> 6, d0 = (idx & 63) * 2;
        float e0 = qb[row * HD + d0] * scale, e1 = qb[row * HD + d0 + 1] * scale;
        uint32_t hw, lw; split_pack(e0, e1, hw, lw);
        *(uint32_t*)(smc + (uint32_t)(row * 136 + d0) * 2) = hw;
        *(uint32_t*)(smc + 17408 + (uint32_t)(row * 136 + d0) * 2) = lw;
    }
    __syncthreads();
    uint32_t qhf[8][4], qlf[8][4];
#pragma unroll
    for (int ds = 0; ds < 8; ds++) {
        uint32_t ad = smb + (uint32_t)((wq * 16 + (g & 1) * 8 + r8) * 136
                                       + ds * 16 + (g >> 1) * 8) * 2;
        ldsm4(qhf[ds], ad);
        ldsm4(qlf[ds], ad + 17408);
    }
    __syncthreads();

    auto cp_tile = [&](int tn, uint32_t dstoff) {
        const int p0 = tn * 64;
#pragma unroll
        for (int q = 0; q < 4; q++) {
            int idx = t + q * 512, row = idx >> 5, c16 = idx & 31;
            int p = p0 + row;
            const float* src = (p < CTX)
                ? (target + ((size_t)b * CTX + p) * HID + h * HD + c16 * 4)
                : (hidden + ((size_t)b * QL + (p - CTX)) * HID + h * HD + c16 * 4);
            CPA16(smb + dstoff + (uint32_t)(row * 512 + c16 * 16), src);
        }
    };
    auto rope_split = [&](int tn, uint32_t rawoff, int s) {
        const float* rawf = (const float*)(smc + rawoff);
        const int p0 = tn * 64;
        char* kh = smc + KHO + (uint32_t)s * 34816;
        char* vh = smc + VHO + (uint32_t)s * 34816;
#pragma unroll
        for (int i = 0; i < 8; i++) {
            int idx = t + i * 512, pos = idx >> 6, d0 = (idx & 63) * 2;
            float2 xv = *(const float2*)(rawf + pos * 128 + d0);
            uint32_t hw, lw; split_pack(xv.x, xv.y, hw, lw);
            uint32_t off = (uint32_t)(pos * 136 + d0) * 2;
            *(uint32_t*)(vh + off) = hw;
            *(uint32_t*)(vh + 17408 + off) = lw;
            float2 xr = (d0 < 64) ? *(const float2*)(rawf + pos * 128 + d0 + 64)
                                  : *(const float2*)(rawf + pos * 128 + d0 - 64);
            float rr0 = (d0 < 64) ? -xr.x : xr.x;
            float rr1 = (d0 < 64) ? -xr.y : xr.y;
            int p = p0 + pos;
            float2 cv = *(const float2*)(cosp + (size_t)p * HD + d0);
            float2 sv = *(const float2*)(sinp + (size_t)p * HD + d0);
            float e0 = xv.x * cv.x + rr0 * sv.x;
            float e1 = xv.y * cv.y + rr1 * sv.y;
            split_pack(e0, e1, hw, lw);
            *(uint32_t*)(kh + off) = hw;
            *(uint32_t*)(kh + 17408 + off) = lw;
        }
    };

    // prologue
    cp_tile(0, RAW0); CPC();
    cp_tile(1, RAW1); CPC();
    CPW1();
    __syncthreads();
    rope_split(0, RAW0, 0);
    __syncthreads();

    float oacc[4][4] = {};
    const int r0 = wq * 16 + (L >> 2), r1 = r0 + 8;
    float m0r = -1e30f, m1r = -1e30f, l0r = 0.0f, l1r = 0.0f;

    for (int tile = 0; tile < NTILE; tile++) {
        const int s = tile & 1;
        if (tile + 2 < NTILE) cp_tile(tile + 2, s ? RAW1 : RAW0);
        CPC();

        // ---- S = Q K^T (B-operand: non-trans ldsm on K[pos][d]) ----
        const uint32_t khb = smb + KHO + (uint32_t)s * 34816;
        float sacc[2][4] = {};
#pragma unroll
        for (int ds = 0; ds < 8; ds++) {
            uint32_t bd = khb + (uint32_t)((wk * 16 + (g >> 1) * 8 + r8) * 136
                                           + ds * 16 + (g & 1) * 8) * 2;
            uint32_t bh4[4], bl4[4];
            ldsm4(bh4, bd);
            ldsm4(bl4, bd + 17408);
            mma16816(sacc[0], qhf[ds], bh4);
            mma16816(sacc[0], qhf[ds], bl4);
            mma16816(sacc[0], qlf[ds], bh4);
            mma16816(sacc[1], qhf[ds], bh4 + 2);
            mma16816(sacc[1], qhf[ds], bl4 + 2);
            mma16816(sacc[1], qlf[ds], bh4 + 2);
        }
        // warp-local row max over this warp's 16 keys
        float mx0 = fmaxf(fmaxf(sacc[0][0], sacc[0][1]), fmaxf(sacc[1][0], sacc[1][1]));
        float mx1 = fmaxf(fmaxf(sacc[0][2], sacc[0][3]), fmaxf(sacc[1][2], sacc[1][3]));
        mx0 = fmaxf(mx0, __shfl_xor_sync(0xffffffffu, mx0, 1));
        mx0 = fmaxf(mx0, __shfl_xor_sync(0xffffffffu, mx0, 2));
        mx1 = fmaxf(mx1, __shfl_xor_sync(0xffffffffu, mx1, 1));
        mx1 = fmaxf(mx1, __shfl_xor_sync(0xffffffffu, mx1, 2));
        if ((L & 3) == 0) { wmx[wk * 64 + r0] = mx0; wmx[wk * 64 + r1] = mx1; }
        NBAR(1 + wq);                                          // bar1 (wq-group only)

        // global max + alpha (redundant per warp, register-resident)
        float gm0 = fmaxf(fmaxf(wmx[r0], wmx[64 + r0]), fmaxf(wmx[128 + r0], wmx[192 + r0]));
        float gm1 = fmaxf(fmaxf(wmx[r1], wmx[64 + r1]), fmaxf(wmx[128 + r1], wmx[192 + r1]));
        float mn0 = fmaxf(m0r, gm0), mn1 = fmaxf(m1r, gm1);
        float al0 = __expf(m0r - mn0), al1 = __expf(m1r - mn1);
        m0r = mn0; m1r = mn1;

        // exp, split-store P, partial row sums
        float s0 = 0.f, s1 = 0.f;
#pragma unroll
        for (int nf = 0; nf < 2; nf++) {
            float e0 = __expf(sacc[nf][0] - mn0), e1 = __expf(sacc[nf][1] - mn0);
            float e2 = __expf(sacc[nf][2] - mn1), e3 = __expf(sacc[nf][3] - mn1);
            s0 += e0 + e1; s1 += e2 + e3;
            int col = wk * 16 + nf * 8 + (L & 3) * 2;
            uint32_t hw, lw;
            split_pack(e0, e1, hw, lw);
            *(uint32_t*)(smc + PHO + (uint32_t)(r0 * 72 + col) * 2) = hw;
            *(uint32_t*)(smc + PLO + (uint32_t)(r0 * 72 + col) * 2) = lw;
            split_pack(e2, e3, hw, lw);
            *(uint32_t*)(smc + PHO + (uint32_t)(r1 * 72 + col) * 2) = hw;
            *(uint32_t*)(smc + PLO + (uint32_t)(r1 * 72 + col) * 2) = lw;
        }
        s0 += __shfl_xor_sync(0xffffffffu, s0, 1);
        s0 += __shfl_xor_sync(0xffffffffu, s0, 2);
        s1 += __shfl_xor_sync(0xffffffffu, s1, 1);
        s1 += __shfl_xor_sync(0xffffffffu, s1, 2);
        if ((L & 3) == 0) { wsm[wk * 64 + r0] = s0; wsm[wk * 64 + r1] = s1; }
        CPW1();                                                 // own cp(i+1) done
        __syncthreads();                                        // bar2 (global: P+sums+cp visible)

        l0r = l0r * al0 + wsm[r0] + wsm[64 + r0] + wsm[128 + r0] + wsm[192 + r0];
        l1r = l1r * al1 + wsm[r1] + wsm[64 + r1] + wsm[128 + r1] + wsm[192 + r1];
#pragma unroll
        for (int nf = 0; nf < 4; nf++) {
            oacc[nf][0] *= al0; oacc[nf][1] *= al0;
            oacc[nf][2] *= al1; oacc[nf][3] *= al1;
        }

        // ---- build next tile K/V first (its latency overlaps PV mma) ----
        if (tile + 1 < NTILE)
            rope_split(tile + 1, s ? RAW0 : RAW1, (tile + 1) & 1);

        // ---- O += P V ----
        const uint32_t vhb = smb + VHO + (uint32_t)s * 34816;
#pragma unroll
        for (int ks = 0; ks < 4; ks++) {
            uint32_t pa = smb + PHO + (uint32_t)((wq * 16 + (g & 1) * 8 + r8) * 72
                                                 + ks * 16 + (g >> 1) * 8) * 2;
            uint32_t ph4[4], pl4[4];
            ldsm4(ph4, pa);
            ldsm4(pl4, pa + (PLO - PHO));
#pragma unroll
            for (int nt = 0; nt < 2; nt++) {
                uint32_t vb = vhb + (uint32_t)((ks * 16 + (L & 15)) * 136
                                               + wk * 32 + nt * 16 + (L >> 4) * 8) * 2;
                uint32_t vh4[4], vl4[4];
                ldsm4t(vh4, vb);
                ldsm4t(vl4, vb + 17408);
                mma16816(oacc[nt * 2], ph4, vh4);
                mma16816(oacc[nt * 2], ph4, vl4);
                mma16816(oacc[nt * 2], pl4, vh4);
                mma16816(oacc[nt * 2 + 1], ph4, vh4 + 2);
                mma16816(oacc[nt * 2 + 1], ph4, vl4 + 2);
                mma16816(oacc[nt * 2 + 1], pl4, vh4 + 2);
            }
        }

        if (tile + 1 < NTILE)
            __syncthreads();                                    // bar3 (K/V publish, raw reuse)
    }

    // ---- epilogue ----
    {
        float inv0 = 1.0f / l0r, inv1 = 1.0f / l1r;
#pragma unroll
        for (int nf = 0; nf < 4; nf++) {
            int d = wk * 32 + nf * 8 + (L & 3) * 2;
            size_t o0 = ((size_t)b * QL + r0) * HID + h * HD + d;
            size_t o1 = ((size_t)b * QL + r1) * HID + h * HD + d;
            *(float2*)&out[o0] = make_float2(oacc[nf][0] * inv0, oacc[nf][1] * inv0);
            *(float2*)&out[o1] = make_float2(oacc[nf][2] * inv1, oacc[nf][3] * inv1);
        }
    }
}

// ---------------------------------------------------------------------------
extern "C" void kernel_launch(void* const* d_in, const int* in_sizes, int n_in,
                              void* d_out, int out_size)
{
    const float* hidden = (const float*)d_in[0];
    const float* target = (const float*)d_in[1];
    const float* cosp   = (const float*)d_in[2];
    const float* sinp   = (const float*)d_in[3];
    const float* Wqkv   = (const float*)d_in[4];
    const float* Wo     = (const float*)d_in[5];
    const float* qnw    = (const float*)d_in[6];
    float* out = (float*)d_out;

    float *qproj, *qrope, *attn;
    cudaGetSymbolAddress((void**)&qproj, g_qproj);
    cudaGetSymbolAddress((void**)&qrope, g_q);
    cudaGetSymbolAddress((void**)&attn,  g_attn);

    cudaFuncSetAttribute(gemm_bf16s, cudaFuncAttributeMaxDynamicSharedMemorySize, GSMEM);
    cudaFuncSetAttribute(attn_kernel, cudaFuncAttributeMaxDynamicSharedMemorySize, ATT_SMEM);

    dim3 gg(HID / 64, (BB * QL) / 128);  // (64, 2)
    gemm_bf16s<<<gg, 256, GSMEM>>>(hidden, Wqkv, qproj, HID, HID, 3 * HID);

    qnorm_rope_kernel<<<BB * QL * NH, 128>>>(qproj, qnw, cosp, sinp, qrope);

    dim3 ga(NH, BB);
    attn_kernel<<<ga, 512, ATT_SMEM>>>(qrope, target, hidden, cosp, sinp, attn);

    gemm_bf16s<<<gg, 256, GSMEM>>>(attn, Wo, out, HID, HID, HID);
}